// round 1
// baseline (speedup 1.0000x reference)
#include <cuda_runtime.h>
#include <cuda_bf16.h>

// LearnableEMA: y[b,0,:] = x[b,0,:]; y[b,t,:] = a*y[b,t-1,:] + (1-a)*x[b,t,:]
// a = clip(sigmoid(logit_alpha), 1e-4, 1-1e-4), per channel.
//
// Single-pass decoupled-lookback scan over T. 268 MB HBM traffic (x in, y out).

#define Bn 16
#define Tn 4096
#define Cn 512
#define TC 64            // chunk length along T
#define NC (Tn / TC)     // 64 chunks
#define CB 128           // channels per block
#define NCT (Cn / CB)    // 4 channel tiles
#define NBLK (Bn * NC * NCT)  // 4096 blocks

// Lookback state (device globals: no allocation allowed).
__device__ float        g_L[Bn * NC * Cn];     // chunk aggregates (carry-in = 0)
__device__ float        g_I[Bn * NC * Cn];     // inclusive prefixes (true y at chunk end)
__device__ int          g_flag[Bn * NC * NCT]; // 0=none, 1=aggregate ready, 2=inclusive ready
__device__ unsigned int g_ticket;

__global__ void ema_init_kernel() {
    int i = blockIdx.x * blockDim.x + threadIdx.x;
    if (i < Bn * NC * NCT) g_flag[i] = 0;
    if (i == 0) g_ticket = 0u;
}

__global__ __launch_bounds__(CB) void ema_scan_kernel(
    const float* __restrict__ x,
    const float* __restrict__ logit_alpha,
    float* __restrict__ y)
{
    __shared__ unsigned int s_vbid;
    __shared__ int s_flag;

    // Ticket: virtual block id in scheduling order (chunk index outermost)
    // => any block only waits on blocks that acquired earlier tickets.
    if (threadIdx.x == 0) s_vbid = atomicAdd(&g_ticket, 1u);
    __syncthreads();
    const unsigned int vbid = s_vbid;

    const int j   = (int)(vbid / (Bn * NCT));   // chunk index (outermost)
    const int rem = (int)(vbid % (Bn * NCT));
    const int b   = rem / NCT;
    const int ct  = rem % NCT;
    const int c   = ct * CB + threadIdx.x;

    // Per-channel alpha
    float la = logit_alpha[c];
    float a  = 1.0f / (1.0f + expf(-la));
    a = fminf(fmaxf(a, 1.0e-4f), 1.0f - 1.0e-4f);
    const float omb = 1.0f - a;

    // A = a^TC via 6 squarings (TC = 64 = 2^6)
    float A = a;
#pragma unroll
    for (int k = 0; k < 6; k++) A = A * A;

    const size_t base = ((size_t)b * Tn + (size_t)j * TC) * Cn + c;
    const float* xp = x + base;
    float*       yp = y + base;

    // ---- Pass A: local scan with zero carry-in, values kept in registers ----
    float loc[TC];
    float l;
    if (j == 0) {
        // y[b,0,c] = x[b,0,c] exactly (coefficient 1, not (1-a))
        l = xp[0];
        loc[0] = l;
#pragma unroll
        for (int i = 1; i < TC; i++) {
            l = fmaf(a, l, omb * xp[(size_t)i * Cn]);
            loc[i] = l;
        }
    } else {
        l = 0.0f;
#pragma unroll
        for (int i = 0; i < TC; i++) {
            l = fmaf(a, l, omb * xp[(size_t)i * Cn]);
            loc[i] = l;
        }
    }

    // ---- Publish aggregate (chunk 0's aggregate is already inclusive) ----
    const int sidx = ((b * NC + j) * Cn) + c;
    const int fidx = (b * NC + j) * NCT + ct;
    if (j < NC - 1) {          // last chunk's state is never consumed
        g_L[sidx] = l;
        if (j == 0) g_I[sidx] = l;
        __threadfence();
        __syncthreads();
        if (threadIdx.x == 0) atomicExch(&g_flag[fidx], (j == 0) ? 2 : 1);
    }

    // ---- Decoupled lookback: carry = true y at end of chunk j-1 ----
    float carry = 0.0f;
    if (j > 0) {
        float w = 1.0f;
        int p = j - 1;
        while (true) {
            if (threadIdx.x == 0) {
                int f;
                do { f = atomicAdd(&g_flag[(b * NC + p) * NCT + ct], 0); } while (f == 0);
                s_flag = f;
            }
            __syncthreads();
            const int f = s_flag;
            __threadfence();  // order flag read before state reads
            if (f == 2) {
                carry = fmaf(w, g_I[((b * NC + p) * Cn) + c], carry);
                break;
            }
            carry = fmaf(w, g_L[((b * NC + p) * Cn) + c], carry);
            w *= A;
            p--;
            if (p < 0) break;   // chunk 0 always ends at flag==2, but be safe
            __syncthreads();    // protect s_flag reuse
        }

        // Publish our inclusive prefix so later blocks stop here.
        if (j < NC - 1) {
            g_I[sidx] = fmaf(A, carry, l);
            __threadfence();
            __syncthreads();
            if (threadIdx.x == 0) atomicExch(&g_flag[fidx], 2);
        }
    }

    // ---- Pass B: y_i = loc_i + a^(i+1) * carry ----
    if (j == 0) {
#pragma unroll
        for (int i = 0; i < TC; i++) yp[(size_t)i * Cn] = loc[i];
    } else {
        float w = a;
#pragma unroll
        for (int i = 0; i < TC; i++) {
            yp[(size_t)i * Cn] = fmaf(w, carry, loc[i]);
            w *= a;
        }
    }
}

extern "C" void kernel_launch(void* const* d_in, const int* in_sizes, int n_in,
                              void* d_out, int out_size) {
    const float* x  = (const float*)d_in[0];
    const float* la = (const float*)d_in[1];
    float*       y  = (float*)d_out;

    ema_init_kernel<<<(Bn * NC * NCT + 255) / 256, 256>>>();
    ema_scan_kernel<<<NBLK, CB>>>(x, la, y);
}

// round 2
// speedup vs baseline: 1.0085x; 1.0085x over previous
#include <cuda_runtime.h>
#include <cuda_bf16.h>

// LearnableEMA: y[b,0,:] = x[b,0,:]; y[b,t,:] = a*y[b,t-1,:] + (1-a)*x[b,t,:]
// a = clip(sigmoid(logit_alpha), 1e-4, 1-1e-4), per channel.
//
// Single-pass decoupled-lookback scan with epsilon-truncated lookback:
// the weight of chunk j-k in the carry is A^(k-1), A = a^64, so lookback
// terminates after a few steps (4 for a=0.9). Aggregates-only protocol —
// no inclusive-prefix chain, no init kernel (epoch-tagged flags).

#define Bn 16
#define Tn 4096
#define Cn 512
#define TC 64            // chunk length along T
#define NC (Tn / TC)     // 64 chunks
#define CB 128           // channels per block
#define NCT (Cn / CB)    // 4 channel tiles
#define NBLK (Bn * NC * NCT)  // 4096 blocks

// Lookback state (device globals: no allocation allowed).
__device__ float        g_L[Bn * NC * Cn];       // chunk aggregates (zero carry-in)
__device__ unsigned int g_flag[Bn * NC * NCT];   // == epoch+1 when aggregate ready
__device__ unsigned int g_ticket;                // monotone across launches

__global__ __launch_bounds__(CB) void ema_scan_kernel(
    const float* __restrict__ x,
    const float* __restrict__ logit_alpha,
    float* __restrict__ y)
{
    __shared__ unsigned int s_raw;

    // Ticket: virtual block id in scheduling order (chunk index outermost)
    // => any block only waits on blocks that acquired earlier tickets.
    // Never reset: epoch = raw / NBLK tags this launch's flags.
    if (threadIdx.x == 0) s_raw = atomicAdd(&g_ticket, 1u);
    __syncthreads();
    const unsigned int raw   = s_raw;
    const unsigned int epoch = raw / NBLK;
    const unsigned int vbid  = raw % NBLK;
    const unsigned int ready = epoch + 1u;

    const int j   = (int)(vbid / (Bn * NCT));   // chunk index (outermost)
    const int rem = (int)(vbid % (Bn * NCT));
    const int b   = rem / NCT;
    const int ct  = rem % NCT;
    const int c   = ct * CB + threadIdx.x;

    // Per-channel alpha
    float la = logit_alpha[c];
    float a  = 1.0f / (1.0f + expf(-la));
    a = fminf(fmaxf(a, 1.0e-4f), 1.0f - 1.0e-4f);
    const float omb = 1.0f - a;

    // A = a^TC via 6 squarings (TC = 64 = 2^6)
    float A = a;
#pragma unroll
    for (int k = 0; k < 6; k++) A = A * A;

    const size_t base = ((size_t)b * Tn + (size_t)j * TC) * Cn + c;
    const float* xp = x + base;
    float*       yp = y + base;

    // ---- Pass A: local scan with zero carry-in, values kept in registers ----
    float loc[TC];
    float l;
    if (j == 0) {
        // y[b,0,c] = x[b,0,c] exactly (coefficient 1, not (1-a))
        l = xp[0];
        loc[0] = l;
#pragma unroll
        for (int i = 1; i < TC; i++) {
            l = fmaf(a, l, omb * xp[(size_t)i * Cn]);
            loc[i] = l;
        }
    } else {
        l = 0.0f;
#pragma unroll
        for (int i = 0; i < TC; i++) {
            l = fmaf(a, l, omb * xp[(size_t)i * Cn]);
            loc[i] = l;
        }
    }

    // ---- Publish aggregate (last chunk's state is never consumed) ----
    const int sidx = ((b * NC + j) * Cn) + c;
    const int fidx = (b * NC + j) * NCT + ct;
    if (j < NC - 1) {
        g_L[sidx] = l;
        __threadfence();
        __syncthreads();
        if (threadIdx.x == 0) atomicExch(&g_flag[fidx], ready);
    }

    // ---- Epsilon-truncated lookback over aggregates only ----
    // carry(end of chunk j-1) = sum_{k>=1} A^(k-1) * L[j-k]; terms below
    // 1e-12 are dropped (bounded truncation, tolerance is 1e-3).
    float carry = 0.0f;
    if (j > 0) {
        float w = 1.0f;
        int p = j - 1;
        while (true) {
            if (threadIdx.x == 0) {
                unsigned int* f = &g_flag[(b * NC + p) * NCT + ct];
                while (atomicAdd(f, 0u) < ready) __nanosleep(32);
            }
            __syncthreads();
            __threadfence();  // order flag observation before aggregate read
            carry = fmaf(w, __ldcg(&g_L[((b * NC + p) * Cn) + c]), carry);
            w *= A;
            p--;
            if (p < 0) break;
            if (__syncthreads_and(fabsf(w) < 1e-12f)) break;
        }
    }

    // ---- Pass B: y_i = loc_i + a^(i+1) * carry ----
    if (j == 0) {
#pragma unroll
        for (int i = 0; i < TC; i++) yp[(size_t)i * Cn] = loc[i];
    } else {
        float w = a;
#pragma unroll
        for (int i = 0; i < TC; i++) {
            yp[(size_t)i * Cn] = fmaf(w, carry, loc[i]);
            w *= a;
        }
    }
}

extern "C" void kernel_launch(void* const* d_in, const int* in_sizes, int n_in,
                              void* d_out, int out_size) {
    const float* x  = (const float*)d_in[0];
    const float* la = (const float*)d_in[1];
    float*       y  = (float*)d_out;

    ema_scan_kernel<<<NBLK, CB>>>(x, la, y);
}